// round 3
// baseline (speedup 1.0000x reference)
#include <cuda_runtime.h>
#include <cuda_fp16.h>
#include <math.h>

#define Nn    50000
#define NPAD  50048            // 782 * 64
#define Ee    1600000
#define F     128
#define ALPHA 0.2f

// ---------------- scratch (static device globals; no allocation) -------------
__device__ __half d_hh[NPAD * F];     // fp16 copy of h (pad rows zero)
__device__ __half d_Wh[F * F];        // fp16 copy of W
__device__ __half d_hwh[NPAD * F];    // fp16 hw = hh @ Wh
__device__ float  d_wa_src[F];        // W @ a_src
__device__ float  d_wa_dst[F];        // W @ a_dst
__device__ float  d_ssrc[Nn];
__device__ float  d_sdst[Nn];
__device__ int    d_rowptr[Nn + 1];
__device__ float  d_sc[Ee];           // per-edge pre-softmax score

// ---------------- PTX helpers ------------------------------------------------
__device__ __forceinline__ unsigned s2u(const void* p) {
    return (unsigned)__cvta_generic_to_shared(p);
}
__device__ __forceinline__ void ldsm_x4(unsigned& r0, unsigned& r1,
                                        unsigned& r2, unsigned& r3, unsigned a) {
    asm volatile("ldmatrix.sync.aligned.m8n8.x4.shared.b16 {%0,%1,%2,%3}, [%4];"
                 : "=r"(r0), "=r"(r1), "=r"(r2), "=r"(r3) : "r"(a));
}
__device__ __forceinline__ void ldsm_x4_t(unsigned& r0, unsigned& r1,
                                          unsigned& r2, unsigned& r3, unsigned a) {
    asm volatile("ldmatrix.sync.aligned.m8n8.x4.trans.shared.b16 {%0,%1,%2,%3}, [%4];"
                 : "=r"(r0), "=r"(r1), "=r"(r2), "=r"(r3) : "r"(a));
}
__device__ __forceinline__ void mma16816(float* c, const unsigned* a,
                                         unsigned b0, unsigned b1) {
    asm volatile(
        "mma.sync.aligned.m16n8k16.row.col.f32.f16.f16.f32 "
        "{%0,%1,%2,%3},{%4,%5,%6,%7},{%8,%9},{%0,%1,%2,%3};"
        : "+f"(c[0]), "+f"(c[1]), "+f"(c[2]), "+f"(c[3])
        : "r"(a[0]), "r"(a[1]), "r"(a[2]), "r"(a[3]), "r"(b0), "r"(b1));
}

// =============================================================================
// K0: wa_src = W @ a_src, wa_dst = W @ a_dst, Wh = fp16(W).  One block.
// =============================================================================
__global__ void prep_kernel(const float* __restrict__ W,
                            const float* __restrict__ a_src,
                            const float* __restrict__ a_dst) {
    const int t = threadIdx.x;   // 128 threads
    for (int i = t; i < F * F; i += 128) d_Wh[i] = __float2half(W[i]);
    float s1 = 0.f, s2 = 0.f;
    #pragma unroll 8
    for (int j = 0; j < F; ++j) {
        float w = W[t * F + j];
        s1 += w * __ldg(&a_src[j]);
        s2 += w * __ldg(&a_dst[j]);
    }
    d_wa_src[t] = s1;
    d_wa_dst[t] = s2;
}

// =============================================================================
// K1: convert h -> fp16 (padded) + exact fp32 scores s_src, s_dst
// one warp per row
// =============================================================================
__global__ __launch_bounds__(256) void conv_kernel(const float* __restrict__ h) {
    const int gw   = (blockIdx.x * blockDim.x + threadIdx.x) >> 5;
    const int lane = threadIdx.x & 31;
    if (gw >= NPAD) return;

    float4 v = make_float4(0.f, 0.f, 0.f, 0.f);
    if (gw < Nn) v = __ldg(&reinterpret_cast<const float4*>(h)[gw * 32 + lane]);

    __half2 p0 = __float22half2_rn(make_float2(v.x, v.y));
    __half2 p1 = __float22half2_rn(make_float2(v.z, v.w));
    uint2 u;
    u.x = *reinterpret_cast<unsigned*>(&p0);
    u.y = *reinterpret_cast<unsigned*>(&p1);
    reinterpret_cast<uint2*>(d_hh)[gw * 32 + lane] = u;

    if (gw < Nn) {
        float4 ws = reinterpret_cast<const float4*>(d_wa_src)[lane];
        float4 wd = reinterpret_cast<const float4*>(d_wa_dst)[lane];
        float ps = v.x * ws.x + v.y * ws.y + v.z * ws.z + v.w * ws.w;
        float pd = v.x * wd.x + v.y * wd.y + v.z * wd.z + v.w * wd.w;
        #pragma unroll
        for (int off = 16; off; off >>= 1) {
            ps += __shfl_xor_sync(0xffffffffu, ps, off);
            pd += __shfl_xor_sync(0xffffffffu, pd, off);
        }
        if (lane == 0) { d_ssrc[gw] = ps; d_sdst[gw] = pd; }
    }
}

// =============================================================================
// K2: hw = hh @ Wh via mma.sync m16n8k16 (fp16 in, fp32 acc, fp16 out)
// block: 256 thr (8 warps), tile 64 rows x 128 cols, K=128 in one smem stage.
// warp grid 2(m) x 4(n): warp tile 32x32.  XOR-swizzled smem, ldmatrix.
// =============================================================================
__global__ __launch_bounds__(256) void hgemm_kernel() {
    __shared__ __align__(16) __half As[64 * F];    // 16 KB
    __shared__ __align__(16) __half Bs[F * F];     // 32 KB

    const int t       = threadIdx.x;
    const int rowBase = blockIdx.x * 64;
    const int lane    = t & 31;
    const int wid     = t >> 5;
    const int wm      = wid >> 2;   // 0..1
    const int wn      = wid & 3;    // 0..3

    // stage A: 64x128 half = 1024 granules of 16B, swizzle g ^= (r&7)
    const uint4* __restrict__ hh4 = reinterpret_cast<const uint4*>(d_hh);
    #pragma unroll
    for (int i = 0; i < 4; ++i) {
        int G = i * 256 + t;
        int r = G >> 4, g = G & 15;
        reinterpret_cast<uint4*>(As)[r * 16 + (g ^ (r & 7))] =
            hh4[(rowBase + r) * 16 + g];
    }
    // stage B: 128x128 half = 2048 granules
    const uint4* __restrict__ Wh4 = reinterpret_cast<const uint4*>(d_Wh);
    #pragma unroll
    for (int i = 0; i < 8; ++i) {
        int G = i * 256 + t;
        int r = G >> 4, g = G & 15;
        reinterpret_cast<uint4*>(Bs)[r * 16 + (g ^ (r & 7))] = Wh4[G];
    }
    __syncthreads();

    const unsigned Ab = s2u(As), Bb = s2u(Bs);
    float c[2][4][4];
    #pragma unroll
    for (int i = 0; i < 2; ++i)
        #pragma unroll
        for (int j = 0; j < 4; ++j)
            #pragma unroll
            for (int q = 0; q < 4; ++q) c[i][j][q] = 0.f;

    #pragma unroll
    for (int kk = 0; kk < 8; ++kk) {
        unsigned a[2][4], b[2][4];
        #pragma unroll
        for (int i = 0; i < 2; ++i) {
            int r = wm * 32 + i * 16 + (lane & 15);
            int g = kk * 2 + (lane >> 4);
            ldsm_x4(a[i][0], a[i][1], a[i][2], a[i][3],
                    Ab + (r * 16 + (g ^ (r & 7))) * 16);
        }
        #pragma unroll
        for (int jp = 0; jp < 2; ++jp) {
            int kr = kk * 16 + (lane & 15);
            int g  = wn * 4 + jp * 2 + (lane >> 4);
            ldsm_x4_t(b[jp][0], b[jp][1], b[jp][2], b[jp][3],
                      Bb + (kr * 16 + (g ^ (kr & 7))) * 16);
        }
        #pragma unroll
        for (int i = 0; i < 2; ++i)
            #pragma unroll
            for (int j = 0; j < 4; ++j)
                mma16816(c[i][j], a[i], b[j >> 1][(j & 1) * 2],
                         b[j >> 1][(j & 1) * 2 + 1]);
    }

    // epilogue: fp16 store (d_hwh padded -> unguarded)
    const int g   = lane >> 2;
    const int cp  = (lane & 3) * 2;
    #pragma unroll
    for (int i = 0; i < 2; ++i)
        #pragma unroll
        for (int j = 0; j < 4; ++j) {
            int gr = rowBase + wm * 32 + i * 16 + g;
            int gc = wn * 32 + j * 8 + cp;
            __half2 lo = __float22half2_rn(make_float2(c[i][j][0], c[i][j][1]));
            __half2 hi = __float22half2_rn(make_float2(c[i][j][2], c[i][j][3]));
            *reinterpret_cast<__half2*>(&d_hwh[gr * F + gc])       = lo;
            *reinterpret_cast<__half2*>(&d_hwh[(gr + 8) * F + gc]) = hi;
        }
}

// =============================================================================
// K3: row_ptr[i] = lower_bound(row, i)
// =============================================================================
__global__ void rowptr_kernel(const int* __restrict__ row) {
    int i = blockIdx.x * blockDim.x + threadIdx.x;
    if (i > Nn) return;
    int lo = 0, hi = Ee;
    while (lo < hi) {
        int mid = (lo + hi) >> 1;
        if (row[mid] < i) lo = mid + 1; else hi = mid;
    }
    d_rowptr[i] = lo;
}

// =============================================================================
// K4: warp-per-node: online softmax + 2-edge-per-iter fp16 gather
// =============================================================================
__global__ __launch_bounds__(256) void edge_kernel(const int* __restrict__ col,
                                                   float* __restrict__ out) {
    const int gw   = (blockIdx.x * blockDim.x + threadIdx.x) >> 5;
    const int lane = threadIdx.x & 31;
    if (gw >= Nn) return;
    const int   eb   = d_rowptr[gw];
    const int   ee   = d_rowptr[gw + 1];
    const float ssrc = d_ssrc[gw];

    // fused score + online max/sum
    float m = -1e30f, sum = 0.f;
    for (int e = eb + lane; e < ee; e += 32) {
        float s = ssrc + __ldg(&d_sdst[__ldg(&col[e])]);
        float v = (s > 0.f) ? s : ALPHA * s;
        d_sc[e] = v;
        float mn = fmaxf(m, v);
        sum = sum * __expf(m - mn) + __expf(v - mn);
        m = mn;
    }
    #pragma unroll
    for (int off = 16; off; off >>= 1) {
        float mo = __shfl_xor_sync(0xffffffffu, m, off);
        float so = __shfl_xor_sync(0xffffffffu, sum, off);
        float mn = fmaxf(m, mo);
        sum = sum * __expf(m - mn) + so * __expf(mo - mn);
        m = mn;
    }
    const float inv = (ee > eb) ? (1.f / sum) : 0.f;

    // gather: lanes 0-15 -> edge j, lanes 16-31 -> edge j+1; uint4 (16B) per lane
    const uint4* __restrict__ hw4 = reinterpret_cast<const uint4*>(d_hwh);
    const int half_id = lane >> 4;
    const int fg      = lane & 15;
    float acc[8] = {0.f, 0.f, 0.f, 0.f, 0.f, 0.f, 0.f, 0.f};

    for (int e0 = eb; e0 < ee; e0 += 32) {
        int e = e0 + lane;
        float wl = 0.f; int cl = 0;
        if (e < ee) {
            wl = __expf(d_sc[e] - m);
            cl = __ldg(&col[e]);
        }
        const int cnt = min(32, ee - e0);
        #pragma unroll 4
        for (int j = 0; j < cnt; j += 2) {
            float w = __shfl_sync(0xffffffffu, wl, j + half_id);
            int   cc = __shfl_sync(0xffffffffu, cl, j + half_id);
            uint4 q = __ldg(&hw4[cc * 16 + fg]);
            float2 f0 = __half22float2(*reinterpret_cast<__half2*>(&q.x));
            float2 f1 = __half22float2(*reinterpret_cast<__half2*>(&q.y));
            float2 f2 = __half22float2(*reinterpret_cast<__half2*>(&q.z));
            float2 f3 = __half22float2(*reinterpret_cast<__half2*>(&q.w));
            acc[0] += w * f0.x; acc[1] += w * f0.y;
            acc[2] += w * f1.x; acc[3] += w * f1.y;
            acc[4] += w * f2.x; acc[5] += w * f2.y;
            acc[6] += w * f3.x; acc[7] += w * f3.y;
        }
    }
    // merge the two half-warps (same feature group at lane and lane^16)
    #pragma unroll
    for (int f = 0; f < 8; ++f)
        acc[f] += __shfl_xor_sync(0xffffffffu, acc[f], 16);

    if (lane < 16) {
        float o[8];
        #pragma unroll
        for (int f = 0; f < 8; ++f) {
            float x = acc[f] * inv;
            o[f] = (x > 0.f) ? x : expm1f(x);
        }
        float4* op = reinterpret_cast<float4*>(&out[gw * F + fg * 8]);
        op[0] = make_float4(o[0], o[1], o[2], o[3]);
        op[1] = make_float4(o[4], o[5], o[6], o[7]);
    }
}

// =============================================================================
extern "C" void kernel_launch(void* const* d_in, const int* in_sizes, int n_in,
                              void* d_out, int out_size) {
    const float* h     = (const float*)d_in[0];
    const float* W     = (const float*)d_in[1];
    const float* a_src = (const float*)d_in[2];
    const float* a_dst = (const float*)d_in[3];
    const int*   row   = (const int*)d_in[4];
    const int*   col   = (const int*)d_in[5];
    float*       out   = (float*)d_out;

    prep_kernel<<<1, 128>>>(W, a_src, a_dst);
    conv_kernel<<<NPAD / 8, 256>>>(h);
    hgemm_kernel<<<NPAD / 64, 256>>>();
    rowptr_kernel<<<(Nn + 1 + 255) / 256, 256>>>(row);
    edge_kernel<<<(Nn * 32 + 255) / 256, 256>>>(col, out);
}

// round 4
// speedup vs baseline: 1.2452x; 1.2452x over previous
#include <cuda_runtime.h>
#include <cuda_fp16.h>
#include <math.h>

#define Nn    50000
#define NPAD  50048            // 782 * 64
#define Ee    1600000
#define F     128
#define ALPHA 0.2f

// ---------------- scratch (static device globals; no allocation) -------------
__device__ __half d_Wh[F * F];        // fp16 copy of W
__device__ __half d_hwh[NPAD * F];    // fp16 hw = h @ W
__device__ float  d_wa_src[F];        // W @ a_src
__device__ float  d_wa_dst[F];        // W @ a_dst
__device__ float  d_ssrc[Nn];
__device__ float  d_sdst[Nn];
__device__ int    d_rowptr[Nn + 1];

// ---------------- PTX helpers ------------------------------------------------
__device__ __forceinline__ unsigned s2u(const void* p) {
    return (unsigned)__cvta_generic_to_shared(p);
}
__device__ __forceinline__ void ldsm_x4(unsigned& r0, unsigned& r1,
                                        unsigned& r2, unsigned& r3, unsigned a) {
    asm volatile("ldmatrix.sync.aligned.m8n8.x4.shared.b16 {%0,%1,%2,%3}, [%4];"
                 : "=r"(r0), "=r"(r1), "=r"(r2), "=r"(r3) : "r"(a));
}
__device__ __forceinline__ void ldsm_x4_t(unsigned& r0, unsigned& r1,
                                          unsigned& r2, unsigned& r3, unsigned a) {
    asm volatile("ldmatrix.sync.aligned.m8n8.x4.trans.shared.b16 {%0,%1,%2,%3}, [%4];"
                 : "=r"(r0), "=r"(r1), "=r"(r2), "=r"(r3) : "r"(a));
}
__device__ __forceinline__ void mma16816(float* c, const unsigned* a,
                                         unsigned b0, unsigned b1) {
    asm volatile(
        "mma.sync.aligned.m16n8k16.row.col.f32.f16.f16.f32 "
        "{%0,%1,%2,%3},{%4,%5,%6,%7},{%8,%9},{%0,%1,%2,%3};"
        : "+f"(c[0]), "+f"(c[1]), "+f"(c[2]), "+f"(c[3])
        : "r"(a[0]), "r"(a[1]), "r"(a[2]), "r"(a[3]), "r"(b0), "r"(b1));
}

// =============================================================================
// K0: blocks 0..15 convert W -> fp16; block 16: wa_src/wa_dst = W @ a  (warp/row)
// =============================================================================
__global__ void prep_kernel(const float* __restrict__ W,
                            const float* __restrict__ a_src,
                            const float* __restrict__ a_dst) {
    const int b = blockIdx.x, t = threadIdx.x;
    if (b < 16) {
        int base = b * 1024 + t * 4;
        float4 v = __ldg(&reinterpret_cast<const float4*>(W)[base >> 2]);
        __half2 p0 = __float22half2_rn(make_float2(v.x, v.y));
        __half2 p1 = __float22half2_rn(make_float2(v.z, v.w));
        uint2 u;
        u.x = *reinterpret_cast<unsigned*>(&p0);
        u.y = *reinterpret_cast<unsigned*>(&p1);
        reinterpret_cast<uint2*>(d_Wh)[base >> 2] = u;
    } else {
        const int w = t >> 5, lane = t & 31;   // 8 warps, 16 rows each
        float4 as = __ldg(&reinterpret_cast<const float4*>(a_src)[lane >> 2 & 31]);
        // each lane handles 4 consecutive cols: cols = lane*4
        float4 a4 = __ldg(&reinterpret_cast<const float4*>(a_src)[lane]);
        float4 d4 = __ldg(&reinterpret_cast<const float4*>(a_dst)[lane]);
        (void)as;
        for (int r = w; r < F; r += 8) {
            float4 wv = __ldg(&reinterpret_cast<const float4*>(W)[r * 32 + lane]);
            float ps = wv.x * a4.x + wv.y * a4.y + wv.z * a4.z + wv.w * a4.w;
            float pd = wv.x * d4.x + wv.y * d4.y + wv.z * d4.z + wv.w * d4.w;
            #pragma unroll
            for (int off = 16; off; off >>= 1) {
                ps += __shfl_xor_sync(0xffffffffu, ps, off);
                pd += __shfl_xor_sync(0xffffffffu, pd, off);
            }
            if (lane == 0) { d_wa_src[r] = ps; d_wa_dst[r] = pd; }
        }
    }
}

// =============================================================================
// K1: fused:  hw = fp16(h) @ fp16(W)  via mma.sync  +  exact fp32 scores
//   A staged from fp32 h with inline conversion; scores s_src = h·wa_src,
//   s_dst = h·wa_dst computed during staging (quad reduce).
//   tile 64 rows x 128 cols, K=128 single stage, 8 warps (2m x 4n).
// =============================================================================
__global__ __launch_bounds__(256) void hgemm_kernel(const float* __restrict__ h) {
    __shared__ __align__(16) __half As[64 * F];    // 16 KB
    __shared__ __align__(16) __half Bs[F * F];     // 32 KB

    const int t       = threadIdx.x;
    const int rowBase = blockIdx.x * 64;
    const int lane    = t & 31;
    const int wid     = t >> 5;
    const int wm      = wid >> 2;
    const int wn      = wid & 3;

    // ---- stage A from fp32 h + score partials --------------------------------
    {
        const int r   = t >> 2;          // 0..63
        const int seg = t & 3;           // 32-col segment
        const int gr  = rowBase + r;
        const bool ok = gr < Nn;
        const float4* __restrict__ h4 = reinterpret_cast<const float4*>(h);
        const float4* __restrict__ ws4 = reinterpret_cast<const float4*>(d_wa_src);
        const float4* __restrict__ wd4 = reinterpret_cast<const float4*>(d_wa_dst);
        uint4* __restrict__ As4 = reinterpret_cast<uint4*>(As);

        float ps = 0.f, pd = 0.f;
        #pragma unroll
        for (int j = 0; j < 8; j += 2) {
            float4 v0 = ok ? __ldg(&h4[gr * 32 + seg * 8 + j])     : make_float4(0,0,0,0);
            float4 v1 = ok ? __ldg(&h4[gr * 32 + seg * 8 + j + 1]) : make_float4(0,0,0,0);
            float4 s0 = ws4[seg * 8 + j],     s1 = ws4[seg * 8 + j + 1];
            float4 q0 = wd4[seg * 8 + j],     q1 = wd4[seg * 8 + j + 1];
            ps += v0.x*s0.x + v0.y*s0.y + v0.z*s0.z + v0.w*s0.w
                + v1.x*s1.x + v1.y*s1.y + v1.z*s1.z + v1.w*s1.w;
            pd += v0.x*q0.x + v0.y*q0.y + v0.z*q0.z + v0.w*q0.w
                + v1.x*q1.x + v1.y*q1.y + v1.z*q1.z + v1.w*q1.w;
            __half2 p0 = __float22half2_rn(make_float2(v0.x, v0.y));
            __half2 p1 = __float22half2_rn(make_float2(v0.z, v0.w));
            __half2 p2 = __float22half2_rn(make_float2(v1.x, v1.y));
            __half2 p3 = __float22half2_rn(make_float2(v1.z, v1.w));
            uint4 u;
            u.x = *reinterpret_cast<unsigned*>(&p0);
            u.y = *reinterpret_cast<unsigned*>(&p1);
            u.z = *reinterpret_cast<unsigned*>(&p2);
            u.w = *reinterpret_cast<unsigned*>(&p3);
            int g = seg * 4 + (j >> 1);
            As4[r * 16 + (g ^ (r & 7))] = u;
        }
        ps += __shfl_xor_sync(0xffffffffu, ps, 1);
        ps += __shfl_xor_sync(0xffffffffu, ps, 2);
        pd += __shfl_xor_sync(0xffffffffu, pd, 1);
        pd += __shfl_xor_sync(0xffffffffu, pd, 2);
        if (seg == 0 && ok) { d_ssrc[gr] = ps; d_sdst[gr] = pd; }
    }
    // ---- stage B from fp16 Wh ------------------------------------------------
    {
        const uint4* __restrict__ Wh4 = reinterpret_cast<const uint4*>(d_Wh);
        uint4* __restrict__ Bs4 = reinterpret_cast<uint4*>(Bs);
        #pragma unroll
        for (int i = 0; i < 8; ++i) {
            int G = i * 256 + t;
            int r = G >> 4, g = G & 15;
            Bs4[r * 16 + (g ^ (r & 7))] = Wh4[G];
        }
    }
    __syncthreads();

    const unsigned Ab = s2u(As), Bb = s2u(Bs);
    float c[2][4][4];
    #pragma unroll
    for (int i = 0; i < 2; ++i)
        #pragma unroll
        for (int j = 0; j < 4; ++j)
            #pragma unroll
            for (int q = 0; q < 4; ++q) c[i][j][q] = 0.f;

    #pragma unroll
    for (int kk = 0; kk < 8; ++kk) {
        unsigned a[2][4], b[2][4];
        #pragma unroll
        for (int i = 0; i < 2; ++i) {
            int r = wm * 32 + i * 16 + (lane & 15);
            int g = kk * 2 + (lane >> 4);
            ldsm_x4(a[i][0], a[i][1], a[i][2], a[i][3],
                    Ab + (r * 16 + (g ^ (r & 7))) * 16);
        }
        #pragma unroll
        for (int jp = 0; jp < 2; ++jp) {
            int kr = kk * 16 + (lane & 15);
            int g  = wn * 4 + jp * 2 + (lane >> 4);
            ldsm_x4_t(b[jp][0], b[jp][1], b[jp][2], b[jp][3],
                      Bb + (kr * 16 + (g ^ (kr & 7))) * 16);
        }
        #pragma unroll
        for (int i = 0; i < 2; ++i)
            #pragma unroll
            for (int j = 0; j < 4; ++j)
                mma16816(c[i][j], a[i], b[j >> 1][(j & 1) * 2],
                         b[j >> 1][(j & 1) * 2 + 1]);
    }

    // epilogue: fp16 store (buffer padded to NPAD -> no guard)
    const int g  = lane >> 2;
    const int cp = (lane & 3) * 2;
    #pragma unroll
    for (int i = 0; i < 2; ++i)
        #pragma unroll
        for (int j = 0; j < 4; ++j) {
            int gr = rowBase + wm * 32 + i * 16 + g;
            int gc = wn * 32 + j * 8 + cp;
            __half2 lo = __float22half2_rn(make_float2(c[i][j][0], c[i][j][1]));
            __half2 hi = __float22half2_rn(make_float2(c[i][j][2], c[i][j][3]));
            *reinterpret_cast<__half2*>(&d_hwh[gr * F + gc])       = lo;
            *reinterpret_cast<__half2*>(&d_hwh[(gr + 8) * F + gc]) = hi;
        }
}

// =============================================================================
// K2: edge-parallel rowptr from sorted row:
//     rows r in (row[i], row[i+1]]  get rowptr[r] = i+1
// =============================================================================
__global__ void rowptr_kernel(const int* __restrict__ row) {
    int i = blockIdx.x * blockDim.x + threadIdx.x;
    if (i >= Ee) return;
    int a = __ldg(&row[i]);
    int b = (i + 1 < Ee) ? __ldg(&row[i + 1]) : Nn;
    for (int r = a + 1; r <= b; ++r) d_rowptr[r] = i + 1;
    if (i == 0)
        for (int r = 0; r <= a; ++r) d_rowptr[r] = 0;
}

// =============================================================================
// K3: warp-per-node: ONLINE softmax fused with fp16 gather (single edge sweep)
// =============================================================================
__global__ __launch_bounds__(256) void edge_kernel(const int* __restrict__ col,
                                                   float* __restrict__ out) {
    const int gw   = (blockIdx.x * blockDim.x + threadIdx.x) >> 5;
    const int lane = threadIdx.x & 31;
    if (gw >= Nn) return;
    const int   eb   = d_rowptr[gw];
    const int   ee   = d_rowptr[gw + 1];
    const float ssrc = d_ssrc[gw];

    const uint4* __restrict__ hw4 = reinterpret_cast<const uint4*>(d_hwh);
    const int half_id = lane >> 4;
    const int fg      = lane & 15;

    float m = -1e30f, sum = 0.f;
    float acc[8] = {0.f, 0.f, 0.f, 0.f, 0.f, 0.f, 0.f, 0.f};

    for (int e0 = eb; e0 < ee; e0 += 32) {
        const int e   = e0 + lane;
        const int cnt = min(32, ee - e0);

        // per-lane score
        float v = -1e30f; int cl = 0;
        if (e < ee) {
            cl = __ldg(&col[e]);
            float s = ssrc + __ldg(&d_sdst[cl]);
            v = (s > 0.f) ? s : ALPHA * s;
        }
        // warp max + online rescale
        float bm = v;
        #pragma unroll
        for (int off = 16; off; off >>= 1)
            bm = fmaxf(bm, __shfl_xor_sync(0xffffffffu, bm, off));
        if (bm > m) {
            const float scale = __expf(m - bm);
            sum *= scale;
            #pragma unroll
            for (int f = 0; f < 8; ++f) acc[f] *= scale;
            m = bm;
        }
        float wl = __expf(v - m);        // 0 for invalid lanes (underflow)
        float bs = wl;
        #pragma unroll
        for (int off = 16; off; off >>= 1)
            bs += __shfl_xor_sync(0xffffffffu, bs, off);
        sum += bs;

        // gather: lanes 0-15 -> edge j, lanes 16-31 -> edge j+1 (16B per lane)
        #pragma unroll 8
        for (int j = 0; j < cnt; j += 2) {
            float w  = __shfl_sync(0xffffffffu, wl, j + half_id);
            int   cc = __shfl_sync(0xffffffffu, cl, j + half_id);
            uint4 q = __ldg(&hw4[cc * 16 + fg]);
            float2 f0 = __half22float2(*reinterpret_cast<__half2*>(&q.x));
            float2 f1 = __half22float2(*reinterpret_cast<__half2*>(&q.y));
            float2 f2 = __half22float2(*reinterpret_cast<__half2*>(&q.z));
            float2 f3 = __half22float2(*reinterpret_cast<__half2*>(&q.w));
            acc[0] += w * f0.x; acc[1] += w * f0.y;
            acc[2] += w * f1.x; acc[3] += w * f1.y;
            acc[4] += w * f2.x; acc[5] += w * f2.y;
            acc[6] += w * f3.x; acc[7] += w * f3.y;
        }
    }

    // merge half-warps
    #pragma unroll
    for (int f = 0; f < 8; ++f)
        acc[f] += __shfl_xor_sync(0xffffffffu, acc[f], 16);

    if (lane < 16) {
        const float inv = (ee > eb) ? (1.f / sum) : 0.f;
        float o[8];
        #pragma unroll
        for (int f = 0; f < 8; ++f) {
            float x = acc[f] * inv;
            o[f] = (x > 0.f) ? x : expm1f(x);
        }
        float4* op = reinterpret_cast<float4*>(&out[gw * F + fg * 8]);
        op[0] = make_float4(o[0], o[1], o[2], o[3]);
        op[1] = make_float4(o[4], o[5], o[6], o[7]);
    }
}

// =============================================================================
extern "C" void kernel_launch(void* const* d_in, const int* in_sizes, int n_in,
                              void* d_out, int out_size) {
    const float* h     = (const float*)d_in[0];
    const float* W     = (const float*)d_in[1];
    const float* a_src = (const float*)d_in[2];
    const float* a_dst = (const float*)d_in[3];
    const int*   row   = (const int*)d_in[4];
    const int*   col   = (const int*)d_in[5];
    float*       out   = (float*)d_out;

    prep_kernel<<<17, 256>>>(W, a_src, a_dst);
    hgemm_kernel<<<NPAD / 64, 256>>>(h);
    rowptr_kernel<<<(Ee + 255) / 256, 256>>>(row);
    edge_kernel<<<(Nn * 32 + 255) / 256, 256>>>(col, out);
}